// round 6
// baseline (speedup 1.0000x reference)
#include <cuda_runtime.h>

// SSIM fully-fused, smem-free kernel for GB300 (sm_103a).
// Each thread produces a 4-column x 32-row output patch by sliding vertically,
// reading 2 float4 per input array per row directly from global. Vertical
// reuse lives in (prev, pairsum) register accumulators, all math packed f32x2.
// Steady loop is ROLLED (unroll 2) so live ranges stay within one iteration
// (no spills at the 96-reg / 5-CTA occupancy point) while unroll-2 lets ptxas
// rename away the cross-iteration accumulator copies.
//
// Algebra (scale-cancelled): with S = 3x3 sum, u = S - 9*center,
//   num = (2*Sx*Sy + 81*C1) * (2*Uxy + 729*C2)
//   den = (Sx^2 + Sy^2 + 81*C1) * (Uss + 729*C2),  Uss = Uxx + Uyy (merged)

#define IMG_H 512
#define IMG_W 960
#define OUT_H 508
#define OUT_W 956
#define W4    (IMG_W / 4)       // row stride in float4 units

#define NTHREADS 128            // 32 lanes wide x 4 strips
#define STRIP_H 32
#define TILE_W 128              // 32 lanes x 4 cols
#define TILE_H (4 * STRIP_H)    // 128 rows per CTA

typedef unsigned long long u64;

__device__ __forceinline__ u64 PK(float lo, float hi) {
    u64 r; asm("mov.b64 %0, {%1, %2};" : "=l"(r) : "f"(lo), "f"(hi)); return r;
}
__device__ __forceinline__ void UPK(u64 a, float& lo, float& hi) {
    asm("mov.b64 {%0, %1}, %2;" : "=f"(lo), "=f"(hi) : "l"(a));
}
// (a.hi, b.lo)
__device__ __forceinline__ u64 SHP(u64 a, u64 b) {
    float alo, ahi, blo, bhi; UPK(a, alo, ahi); UPK(b, blo, bhi);
    return PK(ahi, blo);
}
__device__ __forceinline__ u64 PADD(u64 a, u64 b) {
    u64 r; asm("add.rn.f32x2 %0, %1, %2;" : "=l"(r) : "l"(a), "l"(b)); return r;
}
__device__ __forceinline__ u64 PMUL(u64 a, u64 b) {
    u64 r; asm("mul.rn.f32x2 %0, %1, %2;" : "=l"(r) : "l"(a), "l"(b)); return r;
}
__device__ __forceinline__ u64 PFMA(u64 a, u64 b, u64 c) {
    u64 r; asm("fma.rn.f32x2 %0, %1, %2, %3;" : "=l"(r) : "l"(a), "l"(b), "l"(c)); return r;
}
#define PREF_L2(p) asm volatile("prefetch.global.L2 [%0];" :: "l"(p))

struct SS {
    // (prev, pairsum) running vertical 3-sum state
    u64 hx0p, hx0s, hx1p, hx1s, hx2p, hx2s;
    u64 hy0p, hy0s, hy1p, hy1s, hy2p, hy2s;
    u64 Hss0p, Hss0s, Hss1p, Hss1s;        // merged xx+yy channel
    u64 Hxy0p, Hxy0s, Hxy1p, Hxy1s;
    u64 pXS0, pXS1, pXS2, pYS0, pYS1, pYS2; // prev-row shifted pairs (centers)
    u64 smx0, smx1, smy0, smy1;             // mu sums, 1-row history
    u64 c_m9, c_two, c_81c1, c_729c2;
};

// PHASE 0: load + stage-1 h-sums + accumulate only (rows 0,1)
// PHASE 1: + stage-1 vertical sums, products, stage-2 h-sums (rows 2,3)
// PHASE 2: full, produces output float4
template<int PHASE>
__device__ __forceinline__ void step(SS& s,
    const float4* __restrict__ X4, const float4* __restrict__ Y4,
    int ro, float4& out)
{
    float4 xa = __ldg(X4 + ro), xb = __ldg(X4 + ro + 1);
    float4 ya = __ldg(Y4 + ro), yb = __ldg(Y4 + ro + 1);

    // natural pairs P_i = (v2i, v2i+1), shifted S_i = (v2i+1, v2i+2)
    u64 XP0 = PK(xa.x, xa.y), XS0 = PK(xa.y, xa.z), XP1 = PK(xa.z, xa.w);
    u64 XS1 = PK(xa.w, xb.x), XP2 = PK(xb.x, xb.y), XS2 = PK(xb.y, xb.z);
    u64 XP3 = PK(xb.z, xb.w);
    u64 YP0 = PK(ya.x, ya.y), YS0 = PK(ya.y, ya.z), YP1 = PK(ya.z, ya.w);
    u64 YS1 = PK(ya.w, yb.x), YP2 = PK(yb.x, yb.y), YS2 = PK(yb.y, yb.z);
    u64 YP3 = PK(yb.z, yb.w);

    // horizontal 3-sums at stage-1 col pairs (0,1),(2,3),(4,5)
    u64 nhx0 = PADD(PADD(XP0, XS0), XP1);
    u64 nhx1 = PADD(PADD(XP1, XS1), XP2);
    u64 nhx2 = PADD(PADD(XP2, XS2), XP3);
    u64 nhy0 = PADD(PADD(YP0, YS0), YP1);
    u64 nhy1 = PADD(PADD(YP1, YS1), YP2);
    u64 nhy2 = PADD(PADD(YP2, YS2), YP3);

    if (PHASE >= 1) {
        // stage-1 vertical 3-sums: S = h_t + (h_{t-1} + h_{t-2})
        u64 Sx0 = PADD(nhx0, s.hx0s);
        u64 Sx1 = PADD(nhx1, s.hx1s);
        u64 Sx2 = PADD(nhx2, s.hx2s);
        u64 Sy0 = PADD(nhy0, s.hy0s);
        u64 Sy1 = PADD(nhy1, s.hy1s);
        u64 Sy2 = PADD(nhy2, s.hy2s);

        // u = S - 9*center (centers = prev row shifted pairs)
        u64 ux0 = PFMA(s.pXS0, s.c_m9, Sx0);
        u64 ux1 = PFMA(s.pXS1, s.c_m9, Sx1);
        u64 ux2 = PFMA(s.pXS2, s.c_m9, Sx2);
        u64 uy0 = PFMA(s.pYS0, s.c_m9, Sy0);
        u64 uy1 = PFMA(s.pYS1, s.c_m9, Sy1);
        u64 uy2 = PFMA(s.pYS2, s.c_m9, Sy2);

        // merged channel ss = ux^2 + uy^2; cross channel xy = ux*uy
        u64 tss0 = PFMA(uy0, uy0, PMUL(ux0, ux0));
        u64 tss1 = PFMA(uy1, uy1, PMUL(ux1, ux1));
        u64 tss2 = PFMA(uy2, uy2, PMUL(ux2, ux2));
        u64 txy0 = PMUL(ux0, uy0);
        u64 txy1 = PMUL(ux1, uy1);
        u64 txy2 = PMUL(ux2, uy2);

        // stage-2 horizontal 3-sums for output pairs (0,1) and (2,3)
        u64 nHss0 = PADD(PADD(tss0, SHP(tss0, tss1)), tss1);
        u64 nHss1 = PADD(PADD(tss1, SHP(tss1, tss2)), tss2);
        u64 nHxy0 = PADD(PADD(txy0, SHP(txy0, txy1)), txy1);
        u64 nHxy1 = PADD(PADD(txy1, SHP(txy1, txy2)), txy2);

        if (PHASE == 2) {
            // stage-2 vertical 3-sums
            u64 Uss0 = PADD(nHss0, s.Hss0s);
            u64 Uss1 = PADD(nHss1, s.Hss1s);
            u64 Uxy0 = PADD(nHxy0, s.Hxy0s);
            u64 Uxy1 = PADD(nHxy1, s.Hxy1s);

            // mu sums from previous iteration (stage-1 row o+1)
            u64 n1a = PFMA(PMUL(s.smx0, s.smy0), s.c_two, s.c_81c1);
            u64 d1a = PFMA(s.smy0, s.smy0, PFMA(s.smx0, s.smx0, s.c_81c1));
            u64 n1b = PFMA(PMUL(s.smx1, s.smy1), s.c_two, s.c_81c1);
            u64 d1b = PFMA(s.smy1, s.smy1, PFMA(s.smx1, s.smx1, s.c_81c1));

            u64 n2a = PFMA(Uxy0, s.c_two, s.c_729c2);
            u64 d2a = PADD(Uss0, s.c_729c2);
            u64 n2b = PFMA(Uxy1, s.c_two, s.c_729c2);
            u64 d2b = PADD(Uss1, s.c_729c2);

            u64 numa = PMUL(n1a, n2a), dena = PMUL(d1a, d2a);
            u64 numb = PMUL(n1b, n2b), denb = PMUL(d1b, d2b);

            float n0, n1, n2, n3, d0, d1, d2, d3;
            UPK(numa, n0, n1); UPK(numb, n2, n3);
            UPK(dena, d0, d1); UPK(denb, d2, d3);
            out.x = fminf(fmaxf(1.0f - __fdividef(n0, d0), 0.0f), 2.0f);
            out.y = fminf(fmaxf(1.0f - __fdividef(n1, d1), 0.0f), 2.0f);
            out.z = fminf(fmaxf(1.0f - __fdividef(n2, d2), 0.0f), 2.0f);
            out.w = fminf(fmaxf(1.0f - __fdividef(n3, d3), 0.0f), 2.0f);
        }

        // stage-2 accumulator updates
        s.Hss0s = PADD(nHss0, s.Hss0p);  s.Hss0p = nHss0;
        s.Hss1s = PADD(nHss1, s.Hss1p);  s.Hss1p = nHss1;
        s.Hxy0s = PADD(nHxy0, s.Hxy0p);  s.Hxy0p = nHxy0;
        s.Hxy1s = PADD(nHxy1, s.Hxy1p);  s.Hxy1p = nHxy1;

        // mu sums for next iteration's output (center col +1)
        s.smx0 = SHP(Sx0, Sx1); s.smx1 = SHP(Sx1, Sx2);
        s.smy0 = SHP(Sy0, Sy1); s.smy1 = SHP(Sy1, Sy2);
    }

    // stage-1 accumulator updates (every row)
    s.hx0s = PADD(nhx0, s.hx0p);  s.hx0p = nhx0;
    s.hx1s = PADD(nhx1, s.hx1p);  s.hx1p = nhx1;
    s.hx2s = PADD(nhx2, s.hx2p);  s.hx2p = nhx2;
    s.hy0s = PADD(nhy0, s.hy0p);  s.hy0p = nhy0;
    s.hy1s = PADD(nhy1, s.hy1p);  s.hy1p = nhy1;
    s.hy2s = PADD(nhy2, s.hy2p);  s.hy2p = nhy2;

    // centers for the next stage-1 row
    s.pXS0 = XS0; s.pXS1 = XS1; s.pXS2 = XS2;
    s.pYS0 = YS0; s.pYS1 = YS1; s.pYS2 = YS2;
}

__global__ __launch_bounds__(NTHREADS, 5)
void ssim_kernel(const float* __restrict__ X,
                 const float* __restrict__ Y,
                 float* __restrict__ O)
{
    const int tid   = threadIdx.x;
    const int lane  = tid & 31;
    const int strip = tid >> 5;
    const int img   = blockIdx.z;
    const int oy0   = blockIdx.y * TILE_H + strip * STRIP_H;
    const int ox    = blockIdx.x * TILE_W + 4 * lane;
    const int cx    = min(ox, IMG_W - 8);   // clamp reads; outputs masked
    const bool col_ok = (ox < OUT_W);

    const float4* __restrict__ X4 =
        (const float4*)(X + (size_t)img * (IMG_H * IMG_W) + cx);
    const float4* __restrict__ Y4 =
        (const float4*)(Y + (size_t)img * (IMG_H * IMG_W) + cx);
    float* __restrict__ Ob = O + (size_t)img * (OUT_H * OUT_W) + ox;

    SS s;
    s.hx0p = s.hx0s = s.hx1p = s.hx1s = s.hx2p = s.hx2s = 0;
    s.hy0p = s.hy0s = s.hy1p = s.hy1s = s.hy2p = s.hy2s = 0;
    s.Hss0p = s.Hss0s = s.Hss1p = s.Hss1s = 0;
    s.Hxy0p = s.Hxy0s = s.Hxy1p = s.Hxy1s = 0;
    s.pXS0 = s.pXS1 = s.pXS2 = s.pYS0 = s.pYS1 = s.pYS2 = 0;
    s.smx0 = s.smx1 = s.smy0 = s.smy1 = 0;
    s.c_m9    = PK(-9.0f, -9.0f);
    s.c_two   = PK(2.0f, 2.0f);
    s.c_81c1  = PK(8.1e-3f, 8.1e-3f);     // 81 * 0.01^2
    s.c_729c2 = PK(0.6561f, 0.6561f);     // 729 * 0.03^2

    float4 out;
    // ---- prologue: rows oy0 .. oy0+3 (oy0 <= 480, no clamping needed) ----
    step<0>(s, X4, Y4, (oy0 + 0) * W4, out);
    step<0>(s, X4, Y4, (oy0 + 1) * W4, out);
    step<1>(s, X4, Y4, (oy0 + 2) * W4, out);
    step<1>(s, X4, Y4, (oy0 + 3) * W4, out);

    // ---- steady loop: one output row per iteration ----
    #pragma unroll 2
    for (int t = 4; t < STRIP_H + 4; ++t) {
        const int gy  = min(oy0 + t, IMG_H - 1);
        const int pgy = min(gy + 4, IMG_H - 1);
        PREF_L2((const float*)(X4 + pgy * W4));
        PREF_L2((const float*)(Y4 + pgy * W4));

        step<2>(s, X4, Y4, gy * W4, out);

        const int oy = oy0 + t - 4;
        if (col_ok && oy < OUT_H) {
            *(float4*)(Ob + (size_t)oy * OUT_W) = out;
        }
    }
}

extern "C" void kernel_launch(void* const* d_in, const int* in_sizes, int n_in,
                              void* d_out, int out_size)
{
    const float* x = (const float*)d_in[0];
    const float* y = (const float*)d_in[1];
    float* o = (float*)d_out;

    dim3 grid((OUT_W + TILE_W - 1) / TILE_W,   // 8
              (OUT_H + TILE_H - 1) / TILE_H,   // 4
              48);                             // 16 batch * 3 channels
    ssim_kernel<<<grid, NTHREADS>>>(x, y, o);
}

// round 7
// speedup vs baseline: 1.1861x; 1.1861x over previous
#include <cuda_runtime.h>

// SSIM fully-fused, smem-free kernel for GB300 (sm_103a).
// R7 = R4 resource point (full unroll, <=128 regs, 4 CTA/SM, STRIP_H=16)
//    + R5 merged-channel algebra (ss = ux^2+uy^2 pooled as one channel).
//
// Algebra (scale-cancelled): with S = 3x3 sum, u = S - 9*center,
//   num = (2*Sx*Sy + 81*C1) * (2*Uxy + 729*C2)
//   den = (Sx^2 + Sy^2 + 81*C1) * (Uss + 729*C2),  Uss = Uxx + Uyy (merged)

#define IMG_H 512
#define IMG_W 960
#define OUT_H 508
#define OUT_W 956

#define NTHREADS 128          // 32 lanes wide x 4 strips
#define STRIP_H 16
#define TILE_W 128            // 32 lanes x 4 cols
#define TILE_H 64             // 4 strips x 16 rows

typedef unsigned long long u64;

__device__ __forceinline__ u64 PK(float lo, float hi) {
    u64 r; asm("mov.b64 %0, {%1, %2};" : "=l"(r) : "f"(lo), "f"(hi)); return r;
}
__device__ __forceinline__ void UPK(u64 a, float& lo, float& hi) {
    asm("mov.b64 {%0, %1}, %2;" : "=f"(lo), "=f"(hi) : "l"(a));
}
// (a.hi, b.lo)
__device__ __forceinline__ u64 SHP(u64 a, u64 b) {
    float alo, ahi, blo, bhi; UPK(a, alo, ahi); UPK(b, blo, bhi);
    return PK(ahi, blo);
}
__device__ __forceinline__ u64 PADD(u64 a, u64 b) {
    u64 r; asm("add.rn.f32x2 %0, %1, %2;" : "=l"(r) : "l"(a), "l"(b)); return r;
}
__device__ __forceinline__ u64 PMUL(u64 a, u64 b) {
    u64 r; asm("mul.rn.f32x2 %0, %1, %2;" : "=l"(r) : "l"(a), "l"(b)); return r;
}
__device__ __forceinline__ u64 PFMA(u64 a, u64 b, u64 c) {
    u64 r; asm("fma.rn.f32x2 %0, %1, %2, %3;" : "=l"(r) : "l"(a), "l"(b), "l"(c)); return r;
}
#define PREF_L2(p) asm volatile("prefetch.global.L2 [%0];" :: "l"(p))

__global__ __launch_bounds__(NTHREADS, 4)
void ssim_kernel(const float* __restrict__ X,
                 const float* __restrict__ Y,
                 float* __restrict__ O)
{
    const int tid   = threadIdx.x;
    const int lane  = tid & 31;
    const int strip = tid >> 5;
    const int img   = blockIdx.z;
    const int oy0   = blockIdx.y * TILE_H + strip * STRIP_H;
    const int ox    = blockIdx.x * TILE_W + 4 * lane;
    // Clamp read base so edge threads stay in-bounds (outputs masked later).
    const int cx    = min(ox, IMG_W - 8);

    const float* __restrict__ Xb = X + (size_t)img * (IMG_H * IMG_W) + cx;
    const float* __restrict__ Yb = Y + (size_t)img * (IMG_H * IMG_W) + cx;
    float* __restrict__ Ob = O + (size_t)img * (OUT_H * OUT_W);

    const u64 c_m9    = PK(-9.0f, -9.0f);
    const u64 c_two   = PK(2.0f, 2.0f);
    const u64 c_81c1  = PK(8.1e-3f, 8.1e-3f);     // 81 * 0.01^2
    const u64 c_729c2 = PK(0.6561f, 0.6561f);     // 729 * 0.03^2

    // (prev, pairsum) accumulators: running vertical 3-sum state, 2 regs each.
    u64 hx0p = 0, hx0s = 0, hx1p = 0, hx1s = 0, hx2p = 0, hx2s = 0;
    u64 hy0p = 0, hy0s = 0, hy1p = 0, hy1s = 0, hy2p = 0, hy2s = 0;
    u64 Hss0p = 0, Hss0s = 0, Hss1p = 0, Hss1s = 0;   // merged xx+yy channel
    u64 Hxy0p = 0, Hxy0s = 0, Hxy1p = 0, Hxy1s = 0;
    // Previous-row shifted pairs (centers for u = S - 9*c).
    u64 pXS0 = 0, pXS1 = 0, pXS2 = 0, pYS0 = 0, pYS1 = 0, pYS2 = 0;
    // mu sums from previous stage-1 row.
    u64 smx0 = 0, smx1 = 0, smy0 = 0, smy1 = 0;

    #pragma unroll
    for (int t = 0; t < STRIP_H + 4; ++t) {
        const int gy = min(oy0 + t, IMG_H - 1);
        const size_t roff = (size_t)gy * IMG_W;

        float4 xa = __ldg((const float4*)(Xb + roff));
        float4 xb = __ldg((const float4*)(Xb + roff) + 1);
        float4 ya = __ldg((const float4*)(Yb + roff));
        float4 yb = __ldg((const float4*)(Yb + roff) + 1);

        if (t + 4 < STRIP_H + 4) {   // compile-time under full unroll
            const size_t poff = roff + 4 * (size_t)IMG_W;
            PREF_L2(Xb + poff);
            PREF_L2(Yb + poff);
        }

        // natural pairs P_i = (v2i, v2i+1), shifted S_i = (v2i+1, v2i+2)
        u64 XP0 = PK(xa.x, xa.y), XS0 = PK(xa.y, xa.z), XP1 = PK(xa.z, xa.w);
        u64 XS1 = PK(xa.w, xb.x), XP2 = PK(xb.x, xb.y), XS2 = PK(xb.y, xb.z);
        u64 XP3 = PK(xb.z, xb.w);
        u64 YP0 = PK(ya.x, ya.y), YS0 = PK(ya.y, ya.z), YP1 = PK(ya.z, ya.w);
        u64 YS1 = PK(ya.w, yb.x), YP2 = PK(yb.x, yb.y), YS2 = PK(yb.y, yb.z);
        u64 YP3 = PK(yb.z, yb.w);

        // horizontal 3-sums at stage-1 col pairs (0,1),(2,3),(4,5)
        u64 nhx0 = PADD(PADD(XP0, XS0), XP1);
        u64 nhx1 = PADD(PADD(XP1, XS1), XP2);
        u64 nhx2 = PADD(PADD(XP2, XS2), XP3);
        u64 nhy0 = PADD(PADD(YP0, YS0), YP1);
        u64 nhy1 = PADD(PADD(YP1, YS1), YP2);
        u64 nhy2 = PADD(PADD(YP2, YS2), YP3);

        if (t >= 2) {
            // stage-1 vertical 3-sums: S = h_t + (h_{t-1} + h_{t-2})
            u64 Sx0 = PADD(nhx0, hx0s);
            u64 Sx1 = PADD(nhx1, hx1s);
            u64 Sx2 = PADD(nhx2, hx2s);
            u64 Sy0 = PADD(nhy0, hy0s);
            u64 Sy1 = PADD(nhy1, hy1s);
            u64 Sy2 = PADD(nhy2, hy2s);

            // u = S - 9*center (centers = prev row shifted pairs)
            u64 ux0 = PFMA(pXS0, c_m9, Sx0);
            u64 ux1 = PFMA(pXS1, c_m9, Sx1);
            u64 ux2 = PFMA(pXS2, c_m9, Sx2);
            u64 uy0 = PFMA(pYS0, c_m9, Sy0);
            u64 uy1 = PFMA(pYS1, c_m9, Sy1);
            u64 uy2 = PFMA(pYS2, c_m9, Sy2);

            // merged channel ss = ux^2 + uy^2; cross channel xy = ux*uy
            u64 tss0 = PFMA(uy0, uy0, PMUL(ux0, ux0));
            u64 tss1 = PFMA(uy1, uy1, PMUL(ux1, ux1));
            u64 tss2 = PFMA(uy2, uy2, PMUL(ux2, ux2));
            u64 txy0 = PMUL(ux0, uy0);
            u64 txy1 = PMUL(ux1, uy1);
            u64 txy2 = PMUL(ux2, uy2);

            // stage-2 horizontal 3-sums for output pairs (0,1) and (2,3)
            u64 nHss0 = PADD(PADD(tss0, SHP(tss0, tss1)), tss1);
            u64 nHss1 = PADD(PADD(tss1, SHP(tss1, tss2)), tss2);
            u64 nHxy0 = PADD(PADD(txy0, SHP(txy0, txy1)), txy1);
            u64 nHxy1 = PADD(PADD(txy1, SHP(txy1, txy2)), txy2);

            if (t >= 4) {
                // stage-2 vertical 3-sums: U = H_t + (H_{t-1} + H_{t-2})
                u64 Uss0 = PADD(nHss0, Hss0s);
                u64 Uss1 = PADD(nHss1, Hss1s);
                u64 Uxy0 = PADD(nHxy0, Hxy0s);
                u64 Uxy1 = PADD(nHxy1, Hxy1s);

                // mu sums from previous iteration (stage-1 row o+1)
                u64 n1a = PFMA(PMUL(smx0, smy0), c_two, c_81c1);
                u64 d1a = PFMA(smy0, smy0, PFMA(smx0, smx0, c_81c1));
                u64 n1b = PFMA(PMUL(smx1, smy1), c_two, c_81c1);
                u64 d1b = PFMA(smy1, smy1, PFMA(smx1, smx1, c_81c1));

                u64 n2a = PFMA(Uxy0, c_two, c_729c2);
                u64 d2a = PADD(Uss0, c_729c2);
                u64 n2b = PFMA(Uxy1, c_two, c_729c2);
                u64 d2b = PADD(Uss1, c_729c2);

                u64 numa = PMUL(n1a, n2a), dena = PMUL(d1a, d2a);
                u64 numb = PMUL(n1b, n2b), denb = PMUL(d1b, d2b);

                float n0, n1, n2, n3, d0, d1, d2, d3;
                UPK(numa, n0, n1); UPK(numb, n2, n3);
                UPK(dena, d0, d1); UPK(denb, d2, d3);
                float4 out;
                out.x = fminf(fmaxf(1.0f - __fdividef(n0, d0), 0.0f), 2.0f);
                out.y = fminf(fmaxf(1.0f - __fdividef(n1, d1), 0.0f), 2.0f);
                out.z = fminf(fmaxf(1.0f - __fdividef(n2, d2), 0.0f), 2.0f);
                out.w = fminf(fmaxf(1.0f - __fdividef(n3, d3), 0.0f), 2.0f);

                const int oy = oy0 + t - 4;
                if (oy < OUT_H && ox < OUT_W) {
                    *(float4*)(Ob + (size_t)oy * OUT_W + ox) = out;
                }
            }

            // stage-2 accumulator updates
            Hss0s = PADD(nHss0, Hss0p);  Hss0p = nHss0;
            Hss1s = PADD(nHss1, Hss1p);  Hss1p = nHss1;
            Hxy0s = PADD(nHxy0, Hxy0p);  Hxy0p = nHxy0;
            Hxy1s = PADD(nHxy1, Hxy1p);  Hxy1p = nHxy1;

            // mu sums for next iteration's output (center col +1)
            smx0 = SHP(Sx0, Sx1); smx1 = SHP(Sx1, Sx2);
            smy0 = SHP(Sy0, Sy1); smy1 = SHP(Sy1, Sy2);
        }

        // stage-1 accumulator updates (every iteration)
        hx0s = PADD(nhx0, hx0p);  hx0p = nhx0;
        hx1s = PADD(nhx1, hx1p);  hx1p = nhx1;
        hx2s = PADD(nhx2, hx2p);  hx2p = nhx2;
        hy0s = PADD(nhy0, hy0p);  hy0p = nhy0;
        hy1s = PADD(nhy1, hy1p);  hy1p = nhy1;
        hy2s = PADD(nhy2, hy2p);  hy2p = nhy2;

        // centers for the next stage-1 row
        pXS0 = XS0; pXS1 = XS1; pXS2 = XS2;
        pYS0 = YS0; pYS1 = YS1; pYS2 = YS2;
    }
}

extern "C" void kernel_launch(void* const* d_in, const int* in_sizes, int n_in,
                              void* d_out, int out_size)
{
    const float* x = (const float*)d_in[0];
    const float* y = (const float*)d_in[1];
    float* o = (float*)d_out;

    dim3 grid((OUT_W + TILE_W - 1) / TILE_W,   // 8
              (OUT_H + TILE_H - 1) / TILE_H,   // 8
              48);                             // 16 batch * 3 channels
    ssim_kernel<<<grid, NTHREADS>>>(x, y, o);
}